// round 1
// baseline (speedup 1.0000x reference)
#include <cuda_runtime.h>

#define T_STEPS 168
#define BN 32
#define NH 32
#define NM 64
#define NN 96
#define E_EDGES 384
#define HG 64
#define HL 128
#define G4 512
#define FUT 24
#define G_TOTAL (BN*T_STEPS)   // 5376
#define SLOPEV 0.01f

// ---------------- scratch (__device__ globals; no allocation allowed) ----------
__device__ int   g_edges[2*E_EDGES];
__device__ float g_feat[(long)NH*G_TOTAL*HG];        // [station][g=b*T+t][k]   44 MB
__device__ float g_whhT[NH*HL*G4];                   // [s][k][j]                8 MB
__device__ float g_xpart[(long)NH*T_STEPS*BN*G4];    // [s][t][b][j]           352 MB

// ---------------- K0a: decode edge_index (handles int32 OR int64 layout) ------
__global__ void k_edges(const int* p32) {
    __shared__ int cnt;
    if (threadIdx.x == 0) cnt = 0;
    __syncthreads();
    // If the buffer is int64, words at odd positions (high halves) are all zero
    // within the first 768 words. If int32, they are random values in [0,96).
    if (threadIdx.x < E_EDGES) {
        if (p32[2*threadIdx.x + 1] != 0) atomicAdd(&cnt, 1);
    }
    __syncthreads();
    int is64 = (cnt == 0);
    int i = threadIdx.x;     // 0..767
    g_edges[i] = is64 ? p32[2*i] : p32[i];
}

// ---------------- K0b: transpose Whh -> whhT[s][k][j] --------------------------
__global__ void k_whhT(const float* __restrict__ Whh) {
    int idx = blockIdx.x * blockDim.x + threadIdx.x;
    if (idx >= NH*G4*HL) return;
    int k = idx % HL;
    int j = (idx / HL) % G4;
    int s = idx / (HL*G4);
    g_whhT[(s*HL + k)*G4 + j] = Whh[idx];
}

// ---------------- K1: GNN (scatter-add + GraphConv + leaky_relu) ---------------
__global__ void k_gnn(const float* __restrict__ hyd, const float* __restrict__ met,
                      const float* __restrict__ Wr, const float* __restrict__ Wrel,
                      const float* __restrict__ bg) {
    __shared__ float x_sh[NN];
    __shared__ float agg[NH];
    __shared__ float wr_s[HG], wl_s[HG], bg_s[HG];
    int g   = blockIdx.x;          // (b,t) graph
    int tid = threadIdx.x;         // 128 threads
    if (tid < HG) { wr_s[tid] = Wr[tid]; wl_s[tid] = Wrel[tid]; bg_s[tid] = bg[tid]; }
    if (tid < NN)
        x_sh[tid] = (tid < NH) ? hyd[(long)g*NH + tid] : met[(long)g*NM + (tid - NH)];
    if (tid < NH) agg[tid] = 0.f;
    __syncthreads();
    for (int e = tid; e < E_EDGES; e += blockDim.x) {
        int src = g_edges[e], dst = g_edges[E_EDGES + e];
        if (dst < NH) atomicAdd(&agg[dst], x_sh[src]);
    }
    __syncthreads();
    for (int idx = tid; idx < NH*HG; idx += blockDim.x) {
        int n = idx >> 6, k = idx & 63;
        float v = x_sh[n]*wr_s[k] + agg[n]*wl_s[k] + bg_s[k];
        v = (v > 0.f) ? v : SLOPEV*v;
        g_feat[((long)n*G_TOTAL + g)*HG + k] = v;
    }
}

// ---------------- K2: per-station input GEMM xpart = feat @ Wih.T + bias -------
// Tile: 64 rows x 128 gate-cols, k = 64 (full). 256 threads, 4x8 microtile.
#define RT 64
#define CT 128
__global__ __launch_bounds__(256) void k_xgemm(const float* __restrict__ Wih,
                                               const float* __restrict__ bih,
                                               const float* __restrict__ bhh) {
    __shared__ __align__(16) float A [HG][RT];   // [k][row] 16 KB
    __shared__ __align__(16) float Bm[HG][CT];   // [k][col] 32 KB
    int s  = blockIdx.z;
    int r0 = blockIdx.y * RT;
    int j0 = blockIdx.x * CT;
    int tid = threadIdx.x;
    {
        int kq = tid & 15;     // float4 group along k
        int r  = tid >> 4;     // 0..15
        const float* fa = &g_feat[((long)s*G_TOTAL + r0)*HG];
        for (int rr = r; rr < RT; rr += 16) {
            float4 v = *(const float4*)(fa + (long)rr*HG + kq*4);
            A[kq*4+0][rr] = v.x; A[kq*4+1][rr] = v.y;
            A[kq*4+2][rr] = v.z; A[kq*4+3][rr] = v.w;
        }
        const float* wb = &Wih[((long)s*G4 + j0)*HG];
        for (int rr = r; rr < CT; rr += 16) {
            float4 v = *(const float4*)(wb + (long)rr*HG + kq*4);
            Bm[kq*4+0][rr] = v.x; Bm[kq*4+1][rr] = v.y;
            Bm[kq*4+2][rr] = v.z; Bm[kq*4+3][rr] = v.w;
        }
    }
    __syncthreads();
    int tx = tid & 15, ty = tid >> 4;
    float acc[4][8];
    #pragma unroll
    for (int i = 0; i < 4; i++)
        #pragma unroll
        for (int jj = 0; jj < 8; jj++) acc[i][jj] = 0.f;

    #pragma unroll 8
    for (int k = 0; k < HG; k++) {
        float4 a  = *(float4*)&A[k][ty*4];
        float4 b0 = *(float4*)&Bm[k][tx*8];
        float4 b1 = *(float4*)&Bm[k][tx*8+4];
        float av[4] = {a.x, a.y, a.z, a.w};
        float bv[8] = {b0.x, b0.y, b0.z, b0.w, b1.x, b1.y, b1.z, b1.w};
        #pragma unroll
        for (int i = 0; i < 4; i++)
            #pragma unroll
            for (int jj = 0; jj < 8; jj++) acc[i][jj] += av[i]*bv[jj];
    }
    // bias (bih + bhh) folded here
    float bj[8];
    #pragma unroll
    for (int jj = 0; jj < 8; jj++) {
        int j = j0 + tx*8 + jj;
        bj[jj] = bih[s*G4 + j] + bhh[s*G4 + j];
    }
    #pragma unroll
    for (int i = 0; i < 4; i++) {
        int row = r0 + ty*4 + i;          // g = b*T + t
        int b = row / T_STEPS, t = row % T_STEPS;
        float* outp = &g_xpart[(((long)s*T_STEPS + t)*BN + b)*G4 + j0 + tx*8];
        #pragma unroll
        for (int jj = 0; jj < 8; jj++) outp[jj] = acc[i][jj] + bj[jj];
    }
}

// ---------------- K3: per-(station, 8-batch) LSTM recurrence + head ------------
__device__ __forceinline__ float sigf(float x) { return 1.f/(1.f + __expf(-x)); }
__device__ __forceinline__ float tanhfast(float x) { return 2.f/(1.f + __expf(-2.f*x)) - 1.f; }

__global__ __launch_bounds__(512) void k_lstm(const float* __restrict__ Wlin,
                                              const float* __restrict__ blin,
                                              float* __restrict__ out) {
    __shared__ __align__(16) float h_sh[HL*8];      // [k][b_local]  4 KB
    __shared__ __align__(16) float gate_sh[G4*8];   // [j][b_local] 16 KB
    int s  = blockIdx.x >> 2;
    int bc = blockIdx.x & 3;
    int j  = threadIdx.x;                            // gate row 0..511
    const float* wcol    = &g_whhT[(long)s*HL*G4 + j];               // + k*G4
    const float* xp_base = &g_xpart[(((long)s*T_STEPS)*BN + bc*8)*G4 + j];

    for (int i = j; i < HL*8; i += 512) h_sh[i] = 0.f;
    float c0 = 0.f, c1 = 0.f;
    float xp[8];
    #pragma unroll
    for (int b = 0; b < 8; b++) xp[b] = xp_base[b*G4];
    __syncthreads();

    for (int t = 0; t < T_STEPS; t++) {
        float acc[8];
        #pragma unroll
        for (int b = 0; b < 8; b++) acc[b] = xp[b];
        if (t + 1 < T_STEPS) {                       // prefetch next step's xpart
            const float* nx = xp_base + (long)(t+1)*BN*G4;
            #pragma unroll
            for (int b = 0; b < 8; b++) xp[b] = nx[b*G4];
        }
        #pragma unroll 4
        for (int k = 0; k < HL; k++) {
            float w  = wcol[k*G4];                   // coalesced 128B / warp
            float4 h0 = *(float4*)&h_sh[k*8];        // broadcast
            float4 h1 = *(float4*)&h_sh[k*8 + 4];
            acc[0] += w*h0.x; acc[1] += w*h0.y; acc[2] += w*h0.z; acc[3] += w*h0.w;
            acc[4] += w*h1.x; acc[5] += w*h1.y; acc[6] += w*h1.z; acc[7] += w*h1.w;
        }
        *(float4*)&gate_sh[j*8]     = make_float4(acc[0], acc[1], acc[2], acc[3]);
        *(float4*)&gate_sh[j*8 + 4] = make_float4(acc[4], acc[5], acc[6], acc[7]);
        __syncthreads();
        // each thread updates 2 (hidden, batch) cells; torch gate order i,f,g,o
        #pragma unroll
        for (int q = 0; q < 2; q++) {
            int p   = 2*j + q;
            int hid = p >> 3, bl = p & 7;
            float gi = gate_sh[(       hid)*8 + bl];
            float gf = gate_sh[(  HL + hid)*8 + bl];
            float gg = gate_sh[(2*HL + hid)*8 + bl];
            float go = gate_sh[(3*HL + hid)*8 + bl];
            float c  = q ? c1 : c0;
            c = sigf(gf)*c + sigf(gi)*tanhfast(gg);
            if (q) c1 = c; else c0 = c;
            h_sh[p] = sigf(go)*tanhfast(c);          // p == hid*8 + bl
        }
        __syncthreads();
    }
    // head: pred = lrelu(h_T @ W_lin.T + b_lin), out layout [B][NH][FUT]
    if (j < 8*FUT) {
        int bl = j / FUT, f = j % FUT;
        float sum = blin[f];
        const float* wl = &Wlin[f*HL];
        for (int k = 0; k < HL; k++) sum += h_sh[k*8 + bl]*wl[k];
        sum = (sum > 0.f) ? sum : SLOPEV*sum;
        int b = bc*8 + bl;
        out[((long)b*NH + s)*FUT + f] = sum;
    }
}

// ---------------- launch --------------------------------------------------------
extern "C" void kernel_launch(void* const* d_in, const int* in_sizes, int n_in,
                              void* d_out, int out_size) {
    const float* met  = (const float*)d_in[0];
    const float* hyd  = (const float*)d_in[1];
    const int*   eidx = (const int*)  d_in[2];
    const float* Wr   = (const float*)d_in[3];
    const float* Wrel = (const float*)d_in[4];
    const float* bg   = (const float*)d_in[5];
    const float* Wih  = (const float*)d_in[6];
    const float* Whh  = (const float*)d_in[7];
    const float* bih  = (const float*)d_in[8];
    const float* bhh  = (const float*)d_in[9];
    const float* Wlin = (const float*)d_in[10];
    const float* blin = (const float*)d_in[11];
    float* out = (float*)d_out;

    k_edges<<<1, 768>>>(eidx);
    {
        int total = NH*G4*HL;
        k_whhT<<<(total + 255)/256, 256>>>(Whh);
    }
    k_gnn<<<G_TOTAL, 128>>>(hyd, met, Wr, Wrel, bg);
    dim3 g2(G4/CT, G_TOTAL/RT, NH);   // (4, 84, 32)
    k_xgemm<<<g2, 256>>>(Wih, bih, bhh);
    k_lstm<<<128, 512>>>(Wlin, blin, out);
}

// round 3
// speedup vs baseline: 1.7392x; 1.7392x over previous
#include <cuda_runtime.h>

#define T_STEPS 168
#define BN 32
#define NH 32
#define NM 64
#define NN 96
#define E_EDGES 384
#define HG 64
#define HL 128
#define G4 512
#define FUT 24
#define G_TOTAL (BN*T_STEPS)   // 5376
#define SLOPEV 0.01f

// LSTM smem split: KC k-rows of Whh cached in smem, rest (HL-KC) in registers
#define KC 96
#define LSTM_SMEM ((KC*G4 + HL*8 + G4*8) * 4)    // 217088 B
#define XG_SMEM   (2*64*128*4)                    // 65536 B

typedef unsigned long long ull;

// ---------------- f32x2 helpers (sm_103a packed FMA) ---------------------------
__device__ __forceinline__ ull pack2(float w) {
    ull r; asm("mov.b64 %0,{%1,%1};" : "=l"(r) : "f"(w)); return r;
}
__device__ __forceinline__ ull packf2(float lo, float hi) {
    ull r; asm("mov.b64 %0,{%1,%2};" : "=l"(r) : "f"(lo), "f"(hi)); return r;
}
__device__ __forceinline__ void fma2(ull &c, ull a, ull b) {
    asm("fma.rn.f32x2 %0,%1,%2,%0;" : "+l"(c) : "l"(a), "l"(b));
}
__device__ __forceinline__ void unpack2(ull v, float &lo, float &hi) {
    asm("mov.b64 {%0,%1},%2;" : "=f"(lo), "=f"(hi) : "l"(v));
}

// ---------------- scratch (__device__ globals; no allocation allowed) ----------
__device__ int   g_edges[2*E_EDGES];
__device__ float g_feat[(long)NH*G_TOTAL*HG];        // [station][g=b*T+t][k]
__device__ float g_whhT[NH*HL*G4];                   // [s][k][j]
__device__ float g_xpart[(long)NH*T_STEPS*BN*G4];    // [s][t][b][j]

// ---------------- K0a: decode edge_index (handles int32 OR int64 layout) ------
__global__ void k_edges(const int* p32) {
    __shared__ int cnt;
    if (threadIdx.x == 0) cnt = 0;
    __syncthreads();
    if (threadIdx.x < E_EDGES) {
        if (p32[2*threadIdx.x + 1] != 0) atomicAdd(&cnt, 1);
    }
    __syncthreads();
    int is64 = (cnt == 0);
    int i = threadIdx.x;     // 0..767
    g_edges[i] = is64 ? p32[2*i] : p32[i];
}

// ---------------- K0b: transpose Whh -> whhT[s][k][j] --------------------------
__global__ void k_whhT(const float* __restrict__ Whh) {
    int idx = blockIdx.x * blockDim.x + threadIdx.x;
    if (idx >= NH*G4*HL) return;
    int k = idx % HL;
    int j = (idx / HL) % G4;
    int s = idx / (HL*G4);
    g_whhT[(s*HL + k)*G4 + j] = Whh[idx];
}

// ---------------- K1: GNN (scatter-add + GraphConv + leaky_relu) ---------------
__global__ void k_gnn(const float* __restrict__ hyd, const float* __restrict__ met,
                      const float* __restrict__ Wr, const float* __restrict__ Wrel,
                      const float* __restrict__ bg) {
    __shared__ float x_sh[NN];
    __shared__ float agg[NH];
    __shared__ float wr_s[HG], wl_s[HG], bg_s[HG];
    int g   = blockIdx.x;
    int tid = threadIdx.x;         // 128 threads
    if (tid < HG) { wr_s[tid] = Wr[tid]; wl_s[tid] = Wrel[tid]; bg_s[tid] = bg[tid]; }
    if (tid < NN)
        x_sh[tid] = (tid < NH) ? hyd[(long)g*NH + tid] : met[(long)g*NM + (tid - NH)];
    if (tid < NH) agg[tid] = 0.f;
    __syncthreads();
    for (int e = tid; e < E_EDGES; e += blockDim.x) {
        int src = g_edges[e], dst = g_edges[E_EDGES + e];
        if (dst < NH) atomicAdd(&agg[dst], x_sh[src]);
    }
    __syncthreads();
    for (int idx = tid; idx < NH*HG; idx += blockDim.x) {
        int n = idx >> 6, k = idx & 63;
        float v = x_sh[n]*wr_s[k] + agg[n]*wl_s[k] + bg_s[k];
        v = (v > 0.f) ? v : SLOPEV*v;
        g_feat[((long)n*G_TOTAL + g)*HG + k] = v;
    }
}

// ---------------- K2: per-station input GEMM (128x128 tile, 8x8 f32x2 micro) ---
#define RT 128
#define CT 128
__global__ __launch_bounds__(256) void k_xgemm(const float* __restrict__ Wih,
                                               const float* __restrict__ bih,
                                               const float* __restrict__ bhh) {
    extern __shared__ float sm[];
    float (*A)[RT]  = (float(*)[RT])sm;             // [k][row] 32 KB
    float (*Bm)[CT] = (float(*)[CT])(sm + HG*RT);   // [k][col] 32 KB
    int s  = blockIdx.z;
    int r0 = blockIdx.y * RT;
    int j0 = blockIdx.x * CT;
    int tid = threadIdx.x;
    {
        int kq = tid & 15;     // float4 group along k
        int r  = tid >> 4;     // 0..15
        const float* fa = &g_feat[((long)s*G_TOTAL + r0)*HG];
        #pragma unroll
        for (int rr = r; rr < RT; rr += 16) {
            float4 v = *(const float4*)(fa + (long)rr*HG + kq*4);
            A[kq*4+0][rr] = v.x; A[kq*4+1][rr] = v.y;
            A[kq*4+2][rr] = v.z; A[kq*4+3][rr] = v.w;
        }
        const float* wb = &Wih[((long)s*G4 + j0)*HG];
        #pragma unroll
        for (int rr = r; rr < CT; rr += 16) {
            float4 v = *(const float4*)(wb + (long)rr*HG + kq*4);
            Bm[kq*4+0][rr] = v.x; Bm[kq*4+1][rr] = v.y;
            Bm[kq*4+2][rr] = v.z; Bm[kq*4+3][rr] = v.w;
        }
    }
    __syncthreads();
    int tx = tid & 15, ty = tid >> 4;
    ull acc[8][4];
    #pragma unroll
    for (int i = 0; i < 8; i++)
        #pragma unroll
        for (int c = 0; c < 4; c++) acc[i][c] = 0ull;

    #pragma unroll 4
    for (int k = 0; k < HG; k++) {
        float4 a0 = *(float4*)&A[k][ty*8];
        float4 a1 = *(float4*)&A[k][ty*8 + 4];
        ulonglong2 bv0 = *(ulonglong2*)&Bm[k][tx*8];
        ulonglong2 bv1 = *(ulonglong2*)&Bm[k][tx*8 + 4];
        ull bp[4] = {bv0.x, bv0.y, bv1.x, bv1.y};
        ull ad[8];
        ad[0]=pack2(a0.x); ad[1]=pack2(a0.y); ad[2]=pack2(a0.z); ad[3]=pack2(a0.w);
        ad[4]=pack2(a1.x); ad[5]=pack2(a1.y); ad[6]=pack2(a1.z); ad[7]=pack2(a1.w);
        #pragma unroll
        for (int i = 0; i < 8; i++)
            #pragma unroll
            for (int c = 0; c < 4; c++) fma2(acc[i][c], ad[i], bp[c]);
    }
    // bias (bih + bhh) folded here
    float bj[8];
    #pragma unroll
    for (int jj = 0; jj < 8; jj++) {
        int j = j0 + tx*8 + jj;
        bj[jj] = bih[s*G4 + j] + bhh[s*G4 + j];
    }
    #pragma unroll
    for (int i = 0; i < 8; i++) {
        int row = r0 + ty*8 + i;          // g = b*T + t
        int b = row / T_STEPS, t = row % T_STEPS;
        float o[8];
        #pragma unroll
        for (int c = 0; c < 4; c++) unpack2(acc[i][c], o[2*c], o[2*c+1]);
        float* outp = &g_xpart[(((long)s*T_STEPS + t)*BN + b)*G4 + j0 + tx*8];
        #pragma unroll
        for (int jj = 0; jj < 8; jj++) outp[jj] = o[jj] + bj[jj];
    }
}

// ---------------- K3: per-(station, 8-batch) LSTM recurrence + head ------------
__device__ __forceinline__ float sigf(float x) { return 1.f/(1.f + __expf(-x)); }
__device__ __forceinline__ float tanhfast(float x) { return 2.f/(1.f + __expf(-2.f*x)) - 1.f; }

__global__ __launch_bounds__(512) void k_lstm(const float* __restrict__ Wlin,
                                              const float* __restrict__ blin,
                                              float* __restrict__ out) {
    extern __shared__ float smem[];
    float* ws      = smem;                 // [KC][G4]  192 KB
    float* h_sh    = smem + KC*G4;         // [HL][8]     4 KB
    float* gate_sh = h_sh + HL*8;          // [G4][8]    16 KB

    int s  = blockIdx.x >> 2;
    int bc = blockIdx.x & 3;
    int j  = threadIdx.x;                  // gate row 0..511
    const float* wcol    = &g_whhT[(long)s*HL*G4 + j];               // + k*G4
    const float* xp_base = &g_xpart[(((long)s*T_STEPS)*BN + bc*8)*G4 + j];

    // preload smem-resident weight rows (k = 0..KC-1), once
    for (int k = 0; k < KC; k++) ws[k*G4 + j] = wcol[k*G4];
    // hold remaining (HL-KC) k-rows in registers, pre-packed f32x2, once
    ull wg2[HL-KC];
    #pragma unroll
    for (int kk = 0; kk < HL-KC; kk++) wg2[kk] = pack2(wcol[(KC+kk)*G4]);

    for (int i = j; i < HL*8; i += 512) h_sh[i] = 0.f;
    float c0 = 0.f, c1 = 0.f;
    float xp[8];
    #pragma unroll
    for (int b = 0; b < 8; b++) xp[b] = xp_base[b*G4];
    __syncthreads();

    for (int t = 0; t < T_STEPS; t++) {
        ull acc[4];
        acc[0] = packf2(xp[0], xp[1]);
        acc[1] = packf2(xp[2], xp[3]);
        acc[2] = packf2(xp[4], xp[5]);
        acc[3] = packf2(xp[6], xp[7]);
        if (t + 1 < T_STEPS) {                       // prefetch next step's xpart
            const float* nx = xp_base + (long)(t+1)*BN*G4;
            #pragma unroll
            for (int b = 0; b < 8; b++) xp[b] = nx[b*G4];
        }
        #pragma unroll 8
        for (int k = 0; k < KC; k++) {
            ull w2 = pack2(ws[k*G4 + j]);
            ulonglong2 ha = *(ulonglong2*)&h_sh[k*8];
            ulonglong2 hb = *(ulonglong2*)&h_sh[k*8 + 4];
            fma2(acc[0], w2, ha.x); fma2(acc[1], w2, ha.y);
            fma2(acc[2], w2, hb.x); fma2(acc[3], w2, hb.y);
        }
        #pragma unroll
        for (int kk = 0; kk < HL-KC; kk++) {
            int k = KC + kk;
            ulonglong2 ha = *(ulonglong2*)&h_sh[k*8];
            ulonglong2 hb = *(ulonglong2*)&h_sh[k*8 + 4];
            fma2(acc[0], wg2[kk], ha.x); fma2(acc[1], wg2[kk], ha.y);
            fma2(acc[2], wg2[kk], hb.x); fma2(acc[3], wg2[kk], hb.y);
        }
        ulonglong2 gA; gA.x = acc[0]; gA.y = acc[1];
        ulonglong2 gB; gB.x = acc[2]; gB.y = acc[3];
        *(ulonglong2*)&gate_sh[j*8]     = gA;
        *(ulonglong2*)&gate_sh[j*8 + 4] = gB;
        __syncthreads();
        // each thread updates 2 (hidden, batch) cells; torch gate order i,f,g,o
        #pragma unroll
        for (int q = 0; q < 2; q++) {
            int p   = 2*j + q;
            int hid = p >> 3, bl = p & 7;
            float gi = gate_sh[(       hid)*8 + bl];
            float gf = gate_sh[(  HL + hid)*8 + bl];
            float gg = gate_sh[(2*HL + hid)*8 + bl];
            float go = gate_sh[(3*HL + hid)*8 + bl];
            float c  = q ? c1 : c0;
            c = sigf(gf)*c + sigf(gi)*tanhfast(gg);
            if (q) c1 = c; else c0 = c;
            h_sh[p] = sigf(go)*tanhfast(c);          // p == hid*8 + bl
        }
        __syncthreads();
    }
    // head: pred = lrelu(h_T @ W_lin.T + b_lin), out layout [B][NH][FUT]
    if (j < 8*FUT) {
        int bl = j / FUT, f = j % FUT;
        float sum = blin[f];
        const float* wl = &Wlin[f*HL];
        for (int k = 0; k < HL; k++) sum += h_sh[k*8 + bl]*wl[k];
        sum = (sum > 0.f) ? sum : SLOPEV*sum;
        int b = bc*8 + bl;
        out[((long)b*NH + s)*FUT + f] = sum;
    }
}

// ---------------- launch --------------------------------------------------------
extern "C" void kernel_launch(void* const* d_in, const int* in_sizes, int n_in,
                              void* d_out, int out_size) {
    const float* met  = (const float*)d_in[0];
    const float* hyd  = (const float*)d_in[1];
    const int*   eidx = (const int*)  d_in[2];
    const float* Wr   = (const float*)d_in[3];
    const float* Wrel = (const float*)d_in[4];
    const float* bg   = (const float*)d_in[5];
    const float* Wih  = (const float*)d_in[6];
    const float* Whh  = (const float*)d_in[7];
    const float* bih  = (const float*)d_in[8];
    const float* bhh  = (const float*)d_in[9];
    const float* Wlin = (const float*)d_in[10];
    const float* blin = (const float*)d_in[11];
    float* out = (float*)d_out;

    static int attr_done = 0;
    if (!attr_done) {
        cudaFuncSetAttribute(k_lstm,  cudaFuncAttributeMaxDynamicSharedMemorySize, LSTM_SMEM);
        cudaFuncSetAttribute(k_xgemm, cudaFuncAttributeMaxDynamicSharedMemorySize, XG_SMEM);
        attr_done = 1;
    }

    k_edges<<<1, 768>>>(eidx);
    {
        int total = NH*G4*HL;
        k_whhT<<<(total + 255)/256, 256>>>(Whh);
    }
    k_gnn<<<G_TOTAL, 128>>>(hyd, met, Wr, Wrel, bg);
    dim3 g2(G4/CT, G_TOTAL/RT, NH);   // (4, 42, 32)
    k_xgemm<<<g2, 256, XG_SMEM>>>(Wih, bih, bhh);
    k_lstm<<<128, 512, LSTM_SMEM>>>(Wlin, blin, out);
}